// round 2
// baseline (speedup 1.0000x reference)
#include <cuda_runtime.h>

#define H_IMG 64
#define W_IMG 64
#define CH    128
#define HD    32
#define HEADS 4
#define KS    3
#define DIL   2
#define PAD   2          // dil*(ks-1)/2
#define KK    9

#define TW 32
#define TH 16
#define HALO 2
#define SW (TW + 2*HALO)   // 36
#define SH (TH + 2*HALO)   // 20
#define NTHREADS (TW*TH)   // 512

__global__ __launch_bounds__(NTHREADS, 2)
void dilate_attn_kernel(const float* __restrict__ q,
                        const float* __restrict__ k,
                        const float* __restrict__ v,
                        float* __restrict__ out)
{
    __shared__ float tile[SH * SW];

    const int tx = threadIdx.x;          // 0..31
    const int ty = threadIdx.y;          // 0..15
    const int tid = ty * TW + tx;

    const int tilesX = W_IMG / TW;       // 2
    const int tileX = (blockIdx.x % tilesX) * TW;
    const int tileY = (blockIdx.x / tilesX) * TH;
    const int head = blockIdx.y;
    const int b    = blockIdx.z;

    const int x = tileX + tx;
    const int y = tileY + ty;
    const int pix = y * W_IMG + x;

    const float scale = 0.1767766952966369f; // 32^-0.5

    // base offset for channel 0 of this (b, head) in [B, C, H, W]
    const size_t plane = (size_t)H_IMG * W_IMG;              // 4096
    const size_t base  = ((size_t)b * CH + head * HD) * plane;

    float logit[KK];
#pragma unroll
    for (int i = 0; i < KK; i++) logit[i] = 0.f;

    // ---------------- q·k pass ----------------
    for (int d = 0; d < HD; d++) {
        const float* kd = k + base + (size_t)d * plane;
        // stage k channel tile (with zero halo) into smem
#pragma unroll
        for (int i = tid; i < SH * SW; i += NTHREADS) {
            const int sy = i / SW;
            const int sx = i - sy * SW;
            const int gy = tileY - HALO + sy;
            const int gx = tileX - HALO + sx;
            float val = 0.f;
            if (gy >= 0 && gy < H_IMG && gx >= 0 && gx < W_IMG)
                val = __ldg(kd + gy * W_IMG + gx);
            tile[i] = val;
        }
        const float qd = __ldg(q + base + (size_t)d * plane + pix);
        __syncthreads();
#pragma unroll
        for (int ki = 0; ki < KS; ki++)
#pragma unroll
            for (int kj = 0; kj < KS; kj++)
                logit[ki * KS + kj] = fmaf(qd, tile[(ty + ki * DIL) * SW + (tx + kj * DIL)],
                                           logit[ki * KS + kj]);
        __syncthreads();
    }

    // ---------------- softmax over 9 taps ----------------
    float m = -1e30f;
#pragma unroll
    for (int i = 0; i < KK; i++) {
        logit[i] *= scale;
        m = fmaxf(m, logit[i]);
    }
    float s = 0.f;
    float w[KK];
#pragma unroll
    for (int i = 0; i < KK; i++) {
        w[i] = __expf(logit[i] - m);
        s += w[i];
    }
    const float inv = 1.f / s;
#pragma unroll
    for (int i = 0; i < KK; i++) w[i] *= inv;

    // ---------------- a·v pass ----------------
    float o[HD];
    for (int d = 0; d < HD; d++) {
        const float* vd = v + base + (size_t)d * plane;
#pragma unroll
        for (int i = tid; i < SH * SW; i += NTHREADS) {
            const int sy = i / SW;
            const int sx = i - sy * SW;
            const int gy = tileY - HALO + sy;
            const int gx = tileX - HALO + sx;
            float val = 0.f;
            if (gy >= 0 && gy < H_IMG && gx >= 0 && gx < W_IMG)
                val = __ldg(vd + gy * W_IMG + gx);
            tile[i] = val;
        }
        __syncthreads();
        float acc = 0.f;
#pragma unroll
        for (int ki = 0; ki < KS; ki++)
#pragma unroll
            for (int kj = 0; kj < KS; kj++)
                acc = fmaf(w[ki * KS + kj], tile[(ty + ki * DIL) * SW + (tx + kj * DIL)], acc);
        o[d] = acc;
        __syncthreads();
    }

    // ---------------- store: out[b, y, x, head*32 + d], contiguous 32 floats ----------------
    float* op = out + ((size_t)b * plane + pix) * CH + head * HD;
#pragma unroll
    for (int d = 0; d < HD; d += 4) {
        float4 t;
        t.x = o[d + 0];
        t.y = o[d + 1];
        t.z = o[d + 2];
        t.w = o[d + 3];
        *reinterpret_cast<float4*>(op + d) = t;
    }
}

extern "C" void kernel_launch(void* const* d_in, const int* in_sizes, int n_in,
                              void* d_out, int out_size)
{
    const float* q = (const float*)d_in[0];
    const float* k = (const float*)d_in[1];
    const float* v = (const float*)d_in[2];
    float* out = (float*)d_out;

    dim3 block(TW, TH);
    dim3 grid((W_IMG / TW) * (H_IMG / TH), HEADS, 16 /*B*/);
    dilate_attn_kernel<<<grid, block>>>(q, k, v, out);
}

// round 3
// speedup vs baseline: 1.0004x; 1.0004x over previous
#include <cuda_runtime.h>

#define H_IMG 64
#define W_IMG 64
#define CH    128
#define HD    32
#define HEADS 4
#define KS    3
#define DIL   2
#define PAD   2          // dil*(ks-1)/2
#define KK    9

#define TW 32
#define TH 16
#define HALO 2
#define SW (TW + 2*HALO)   // 36
#define SH (TH + 2*HALO)   // 20
#define NTHREADS (TW*TH)   // 512

__global__ __launch_bounds__(NTHREADS, 2)
void dilate_attn_kernel(const float* __restrict__ q,
                        const float* __restrict__ k,
                        const float* __restrict__ v,
                        float* __restrict__ out)
{
    __shared__ float tile[SH * SW];

    const int tx = threadIdx.x;          // 0..31
    const int ty = threadIdx.y;          // 0..15
    const int tid = ty * TW + tx;

    const int tilesX = W_IMG / TW;       // 2
    const int tileX = (blockIdx.x % tilesX) * TW;
    const int tileY = (blockIdx.x / tilesX) * TH;
    const int head = blockIdx.y;
    const int b    = blockIdx.z;

    const int x = tileX + tx;
    const int y = tileY + ty;
    const int pix = y * W_IMG + x;

    const float scale = 0.1767766952966369f; // 32^-0.5

    // base offset for channel 0 of this (b, head) in [B, C, H, W]
    const size_t plane = (size_t)H_IMG * W_IMG;              // 4096
    const size_t base  = ((size_t)b * CH + head * HD) * plane;

    float logit[KK];
#pragma unroll
    for (int i = 0; i < KK; i++) logit[i] = 0.f;

    // ---------------- q·k pass ----------------
    for (int d = 0; d < HD; d++) {
        const float* kd = k + base + (size_t)d * plane;
        // stage k channel tile (with zero halo) into smem
#pragma unroll
        for (int i = tid; i < SH * SW; i += NTHREADS) {
            const int sy = i / SW;
            const int sx = i - sy * SW;
            const int gy = tileY - HALO + sy;
            const int gx = tileX - HALO + sx;
            float val = 0.f;
            if (gy >= 0 && gy < H_IMG && gx >= 0 && gx < W_IMG)
                val = __ldg(kd + gy * W_IMG + gx);
            tile[i] = val;
        }
        const float qd = __ldg(q + base + (size_t)d * plane + pix);
        __syncthreads();
#pragma unroll
        for (int ki = 0; ki < KS; ki++)
#pragma unroll
            for (int kj = 0; kj < KS; kj++)
                logit[ki * KS + kj] = fmaf(qd, tile[(ty + ki * DIL) * SW + (tx + kj * DIL)],
                                           logit[ki * KS + kj]);
        __syncthreads();
    }

    // ---------------- softmax over 9 taps ----------------
    float m = -1e30f;
#pragma unroll
    for (int i = 0; i < KK; i++) {
        logit[i] *= scale;
        m = fmaxf(m, logit[i]);
    }
    float s = 0.f;
    float w[KK];
#pragma unroll
    for (int i = 0; i < KK; i++) {
        w[i] = __expf(logit[i] - m);
        s += w[i];
    }
    const float inv = 1.f / s;
#pragma unroll
    for (int i = 0; i < KK; i++) w[i] *= inv;

    // ---------------- a·v pass ----------------
    float o[HD];
    for (int d = 0; d < HD; d++) {
        const float* vd = v + base + (size_t)d * plane;
#pragma unroll
        for (int i = tid; i < SH * SW; i += NTHREADS) {
            const int sy = i / SW;
            const int sx = i - sy * SW;
            const int gy = tileY - HALO + sy;
            const int gx = tileX - HALO + sx;
            float val = 0.f;
            if (gy >= 0 && gy < H_IMG && gx >= 0 && gx < W_IMG)
                val = __ldg(vd + gy * W_IMG + gx);
            tile[i] = val;
        }
        __syncthreads();
        float acc = 0.f;
#pragma unroll
        for (int ki = 0; ki < KS; ki++)
#pragma unroll
            for (int kj = 0; kj < KS; kj++)
                acc = fmaf(w[ki * KS + kj], tile[(ty + ki * DIL) * SW + (tx + kj * DIL)], acc);
        o[d] = acc;
        __syncthreads();
    }

    // ---------------- store: out[b, y, x, head*32 + d], contiguous 32 floats ----------------
    float* op = out + ((size_t)b * plane + pix) * CH + head * HD;
#pragma unroll
    for (int d = 0; d < HD; d += 4) {
        float4 t;
        t.x = o[d + 0];
        t.y = o[d + 1];
        t.z = o[d + 2];
        t.w = o[d + 3];
        *reinterpret_cast<float4*>(op + d) = t;
    }
}

extern "C" void kernel_launch(void* const* d_in, const int* in_sizes, int n_in,
                              void* d_out, int out_size)
{
    const float* q = (const float*)d_in[0];
    const float* k = (const float*)d_in[1];
    const float* v = (const float*)d_in[2];
    float* out = (float*)d_out;

    dim3 block(TW, TH);
    dim3 grid((W_IMG / TW) * (H_IMG / TH), HEADS, 16 /*B*/);
    dilate_attn_kernel<<<grid, block>>>(q, k, v, out);
}

// round 4
// speedup vs baseline: 2.4114x; 2.4105x over previous
#include <cuda_runtime.h>

#define H_IMG 64
#define W_IMG 64
#define CH    128
#define HD    32
#define HEADS 4
#define KS    3
#define DIL   2
#define KK    9

#define TW 32
#define TH 16
#define NTHREADS (TW*TH)      // 512

#define CPC 8                 // channels staged per stage
#define NSTAGE (HD/CPC)       // 4
#define SH (TH + 4)           // 20 rows (halo 2 each side)
#define SWP 40                // padded row: gx in [tileX-4, tileX+36), float4-aligned
#define SEGS (SWP/4)          // 10 float4 segments per row
#define STAGE_ELEMS (CPC*SH*SEGS)   // 1600 float4 slots
#define SMEM_FLOATS (CPC*SH*SWP)    // 6400 floats = 25.6 KB

__global__ __launch_bounds__(NTHREADS, 3)
void dilate_attn_kernel(const float* __restrict__ q,
                        const float* __restrict__ k,
                        const float* __restrict__ v,
                        float* __restrict__ out)
{
    __shared__ float tile[SMEM_FLOATS];

    const int tx  = threadIdx.x;            // 0..31
    const int ty  = threadIdx.y;            // 0..15
    const int tid = ty * TW + tx;

    const int tilesX = W_IMG / TW;          // 2
    const int tileX = (blockIdx.x % tilesX) * TW;
    const int tileY = (blockIdx.x / tilesX) * TH;
    const int head  = blockIdx.y;
    const int b     = blockIdx.z;

    const int x   = tileX + tx;
    const int y   = tileY + ty;
    const int pix = y * W_IMG + x;

    const float scale = 0.1767766952966369f;   // 32^-0.5

    const size_t plane = (size_t)H_IMG * W_IMG;              // 4096
    const size_t base  = ((size_t)b * CH + head * HD) * plane;

    float logit[KK];
#pragma unroll
    for (int i = 0; i < KK; i++) logit[i] = 0.f;

    // ================= q·k pass: 4 stages of 8 channels =================
    for (int st = 0; st < NSTAGE; st++) {
        const int c0 = st * CPC;
        const float* kbase = k + base + (size_t)c0 * plane;

        // stage 8 k-channel tiles (float4, fully-in/out segments)
#pragma unroll
        for (int ii = 0; ii < 4; ii++) {
            const int i = tid + ii * NTHREADS;
            if (i < STAGE_ELEMS) {
                const int ch  = i / (SH * SEGS);
                const int rem = i - ch * (SH * SEGS);
                const int row = rem / SEGS;
                const int seg = rem - row * SEGS;
                const int gy  = tileY - 2 + row;
                const int gx4 = tileX - 4 + seg * 4;
                float4 val = make_float4(0.f, 0.f, 0.f, 0.f);
                if (gy >= 0 && gy < H_IMG && gx4 >= 0 && gx4 + 3 < W_IMG)
                    val = *reinterpret_cast<const float4*>(
                        kbase + (size_t)ch * plane + gy * W_IMG + gx4);
                *reinterpret_cast<float4*>(&tile[ch * (SH * SWP) + row * SWP + seg * 4]) = val;
            }
        }

        // q values for this stage's channels (independent of smem)
        float qv[CPC];
#pragma unroll
        for (int c = 0; c < CPC; c++)
            qv[c] = __ldg(q + base + (size_t)(c0 + c) * plane + pix);

        __syncthreads();
#pragma unroll
        for (int c = 0; c < CPC; c++) {
            const float* tc = &tile[c * (SH * SWP)];
#pragma unroll
            for (int ki = 0; ki < KS; ki++)
#pragma unroll
                for (int kj = 0; kj < KS; kj++)
                    logit[ki * KS + kj] = fmaf(qv[c],
                        tc[(ty + ki * DIL) * SWP + (tx + kj * DIL + 2)],
                        logit[ki * KS + kj]);
        }
        __syncthreads();
    }

    // ================= softmax over 9 taps =================
    float m = -1e30f;
#pragma unroll
    for (int i = 0; i < KK; i++) {
        logit[i] *= scale;
        m = fmaxf(m, logit[i]);
    }
    float s = 0.f;
    float w[KK];
#pragma unroll
    for (int i = 0; i < KK; i++) {
        w[i] = __expf(logit[i] - m);
        s += w[i];
    }
    const float inv = 1.f / s;
#pragma unroll
    for (int i = 0; i < KK; i++) w[i] *= inv;

    // ================= a·v pass: 4 stages, store 8 channels per stage =================
    float* op = out + ((size_t)b * plane + pix) * CH + head * HD;

    for (int st = 0; st < NSTAGE; st++) {
        const int c0 = st * CPC;
        const float* vbase = v + base + (size_t)c0 * plane;

#pragma unroll
        for (int ii = 0; ii < 4; ii++) {
            const int i = tid + ii * NTHREADS;
            if (i < STAGE_ELEMS) {
                const int ch  = i / (SH * SEGS);
                const int rem = i - ch * (SH * SEGS);
                const int row = rem / SEGS;
                const int seg = rem - row * SEGS;
                const int gy  = tileY - 2 + row;
                const int gx4 = tileX - 4 + seg * 4;
                float4 val = make_float4(0.f, 0.f, 0.f, 0.f);
                if (gy >= 0 && gy < H_IMG && gx4 >= 0 && gx4 + 3 < W_IMG)
                    val = *reinterpret_cast<const float4*>(
                        vbase + (size_t)ch * plane + gy * W_IMG + gx4);
                *reinterpret_cast<float4*>(&tile[ch * (SH * SWP) + row * SWP + seg * 4]) = val;
            }
        }
        __syncthreads();

        float o[CPC];
#pragma unroll
        for (int c = 0; c < CPC; c++) {
            const float* tc = &tile[c * (SH * SWP)];
            float acc = 0.f;
#pragma unroll
            for (int ki = 0; ki < KS; ki++)
#pragma unroll
                for (int kj = 0; kj < KS; kj++)
                    acc = fmaf(w[ki * KS + kj],
                               tc[(ty + ki * DIL) * SWP + (tx + kj * DIL + 2)], acc);
            o[c] = acc;
        }
        __syncthreads();

        // store 8 contiguous output channels: 2 x float4
        float4 t0 = make_float4(o[0], o[1], o[2], o[3]);
        float4 t1 = make_float4(o[4], o[5], o[6], o[7]);
        *reinterpret_cast<float4*>(op + c0)     = t0;
        *reinterpret_cast<float4*>(op + c0 + 4) = t1;
    }
}

extern "C" void kernel_launch(void* const* d_in, const int* in_sizes, int n_in,
                              void* d_out, int out_size)
{
    const float* q = (const float*)d_in[0];
    const float* k = (const float*)d_in[1];
    const float* v = (const float*)d_in[2];
    float* out = (float*)d_out;

    dim3 block(TW, TH);
    dim3 grid((W_IMG / TW) * (H_IMG / TH), HEADS, 16 /*B*/);
    dilate_attn_kernel<<<grid, block>>>(q, k, v, out);
}